// round 1
// baseline (speedup 1.0000x reference)
#include <cuda_runtime.h>
#include <cuda_bf16.h>

#define NN 100000
#define EE 800000
#define DD 64
#define HH 4

// Scratch (device globals; no allocation allowed)
__device__ float g_Q[NN * DD];
__device__ float g_K[NN * DD];
__device__ float g_V[NN * DD];
__device__ int   g_cnt[NN];
__device__ int   g_off[NN + 1];
__device__ int   g_cur[NN];
__device__ int   g_bsum[128];
__device__ int   g_scol[EE];

// ---------------------------------------------------------------------------
// 1) Node projections: Q = X Wq, K = X Wk, V = X Wv.  One thread per node.
//    Weights staged in shared (48 KB), x row in registers, float4 LDS broadcast.
// ---------------------------------------------------------------------------
__global__ __launch_bounds__(128) void proj_kernel(
    const float* __restrict__ X,
    const float* __restrict__ Wq,
    const float* __restrict__ Wk,
    const float* __restrict__ Wv)
{
    __shared__ float4 sW[3][DD][DD / 4];   // [matrix][k][d4]
    int tid = threadIdx.x;
    for (int i = tid; i < DD * DD / 4; i += blockDim.x) {
        ((float4*)&sW[0][0][0])[i] = ((const float4*)Wq)[i];
        ((float4*)&sW[1][0][0])[i] = ((const float4*)Wk)[i];
        ((float4*)&sW[2][0][0])[i] = ((const float4*)Wv)[i];
    }
    __syncthreads();

    int node = blockIdx.x * blockDim.x + tid;
    if (node >= NN) return;

    float x[DD];
    const float4* xr = (const float4*)(X + (size_t)node * DD);
#pragma unroll
    for (int i = 0; i < DD / 4; i++) {
        float4 t = xr[i];
        x[4 * i + 0] = t.x; x[4 * i + 1] = t.y;
        x[4 * i + 2] = t.z; x[4 * i + 3] = t.w;
    }

#pragma unroll
    for (int m = 0; m < 3; m++) {
        float* out = (m == 0 ? g_Q : (m == 1 ? g_K : g_V)) + (size_t)node * DD;
        for (int d4 = 0; d4 < DD / 4; d4++) {
            float4 acc = make_float4(0.f, 0.f, 0.f, 0.f);
#pragma unroll
            for (int k = 0; k < DD; k++) {
                float4 w = sW[m][k][d4];
                acc.x += x[k] * w.x;
                acc.y += x[k] * w.y;
                acc.z += x[k] * w.z;
                acc.w += x[k] * w.w;
            }
            ((float4*)out)[d4] = acc;
        }
    }
}

// ---------------------------------------------------------------------------
// 2) CSR build: zero counts -> histogram -> block scan -> scan block sums ->
//    add offsets (+cursor init) -> scatter cols sorted by destination row.
// ---------------------------------------------------------------------------
__global__ void zero_cnt_kernel()
{
    int i = blockIdx.x * blockDim.x + threadIdx.x;
    if (i < NN) g_cnt[i] = 0;
}

__global__ void hist_kernel(const int* __restrict__ rows)
{
    int e = blockIdx.x * blockDim.x + threadIdx.x;
    if (e < EE) atomicAdd(&g_cnt[rows[e]], 1);
}

__global__ __launch_bounds__(1024) void scan_block_kernel()
{
    __shared__ int s[1024];
    int i = blockIdx.x * 1024 + threadIdx.x;
    int v = (i < NN) ? g_cnt[i] : 0;
    s[threadIdx.x] = v;
    __syncthreads();
#pragma unroll
    for (int o = 1; o < 1024; o <<= 1) {
        int t = (threadIdx.x >= o) ? s[threadIdx.x - o] : 0;
        __syncthreads();
        s[threadIdx.x] += t;
        __syncthreads();
    }
    if (i < NN) g_off[i] = s[threadIdx.x] - v;   // exclusive within block
    if (threadIdx.x == 1023) g_bsum[blockIdx.x] = s[1023];
}

__global__ void scan_sums_kernel(int nb)
{
    if (threadIdx.x == 0 && blockIdx.x == 0) {
        int acc = 0;
        for (int b = 0; b < nb; b++) { int t = g_bsum[b]; g_bsum[b] = acc; acc += t; }
    }
}

__global__ void add_off_kernel()
{
    int i = blockIdx.x * blockDim.x + threadIdx.x;
    if (i < NN) {
        int o = g_off[i] + g_bsum[i >> 10];
        g_off[i] = o;
        g_cur[i] = o;
    }
    if (i == 0) g_off[NN] = EE;
}

__global__ void scatter_kernel(const int* __restrict__ rows,
                               const int* __restrict__ cols)
{
    int e = blockIdx.x * blockDim.x + threadIdx.x;
    if (e < EE) {
        int p = atomicAdd(&g_cur[rows[e]], 1);
        g_scol[p] = cols[e];
    }
}

// ---------------------------------------------------------------------------
// 3) Fused attention aggregate: one warp per destination node.
//    lane l owns d = {2l, 2l+1}; head = l/8. Per-head dot via shfl_xor(1,2,4).
//    Accumulates softmax numerator (acc) and denominator (na) in one pass.
// ---------------------------------------------------------------------------
__global__ __launch_bounds__(256) void aggregate_kernel(float* __restrict__ out)
{
    int warp = (blockIdx.x * blockDim.x + threadIdx.x) >> 5;
    int lane = threadIdx.x & 31;
    if (warp >= NN) return;

    int start = g_off[warp];
    int end   = g_off[warp + 1];

    float2 q = *(const float2*)(g_Q + (size_t)warp * DD + lane * 2);
    float2 acc = make_float2(0.f, 0.f);
    float  na  = 0.f;

    for (int j = start; j < end; j++) {
        int c = __ldg(&g_scol[j]);
        const float2 k2 = *(const float2*)(g_K + (size_t)c * DD + lane * 2);
        float p = q.x * k2.x + q.y * k2.y;
        p += __shfl_xor_sync(0xffffffffu, p, 1);
        p += __shfl_xor_sync(0xffffffffu, p, 2);
        p += __shfl_xor_sync(0xffffffffu, p, 4);
        p = fminf(10.f, fmaxf(-10.f, p));
        float ea = __expf(p);
        na += ea;
        const float2 v2 = *(const float2*)(g_V + (size_t)c * DD + lane * 2);
        acc.x += ea * v2.x;
        acc.y += ea * v2.y;
    }

    float inv = 1.f / (na + 1e-8f);
    float2 o = make_float2(acc.x * inv, acc.y * inv);
    *(float2*)(out + (size_t)warp * DD + lane * 2) = o;
}

// ---------------------------------------------------------------------------
extern "C" void kernel_launch(void* const* d_in, const int* in_sizes, int n_in,
                              void* d_out, int out_size)
{
    const float* X  = (const float*)d_in[0];
    const float* Wq = (const float*)d_in[1];
    const float* Wk = (const float*)d_in[2];
    const float* Wv = (const float*)d_in[3];
    const int*   ei = (const int*)d_in[4];
    const int* rows = ei;
    const int* cols = ei + EE;
    float* out = (float*)d_out;

    (void)in_sizes; (void)n_in; (void)out_size;

    // 1) node projections
    proj_kernel<<<(NN + 127) / 128, 128>>>(X, Wq, Wk, Wv);

    // 2) CSR build by destination row
    zero_cnt_kernel<<<(NN + 255) / 256, 256>>>();
    hist_kernel<<<(EE + 255) / 256, 256>>>(rows);
    int nb = (NN + 1023) / 1024;
    scan_block_kernel<<<nb, 1024>>>();
    scan_sums_kernel<<<1, 32>>>(nb);
    add_off_kernel<<<(NN + 255) / 256, 256>>>();
    scatter_kernel<<<(EE + 255) / 256, 256>>>(rows, cols);

    // 3) fused gather + softmax + aggregate (one warp per node)
    aggregate_kernel<<<(NN * 32 + 255) / 256, 256>>>(out);
}

// round 4
// speedup vs baseline: 1.5083x; 1.5083x over previous
#include <cuda_runtime.h>
#include <cuda_bf16.h>

#define NN 100000
#define EE 800000
#define DD 64
#define HH 4

// Scratch (device globals; no allocation allowed)
__device__ float g_Q[NN * DD];
__device__ float g_K[NN * DD];
__device__ float g_V[NN * DD];
__device__ int   g_cnt[NN];
__device__ int   g_off[NN + 1];
__device__ int   g_cur[NN];
__device__ int   g_bsum[128];
__device__ int   g_scol[EE];

// ---------------------------------------------------------------------------
// Packed f32x2 helpers (sm_103a): ptxas never auto-fuses these.
// ---------------------------------------------------------------------------
__device__ __forceinline__ unsigned long long ffma2(
    unsigned long long a, unsigned long long b, unsigned long long c)
{
    unsigned long long d;
    asm("fma.rn.f32x2 %0, %1, %2, %3;" : "=l"(d) : "l"(a), "l"(b), "l"(c));
    return d;
}

__device__ __forceinline__ float unpack_sum(unsigned long long a)
{
    float lo, hi;
    asm("mov.b64 {%0, %1}, %2;" : "=f"(lo), "=f"(hi) : "l"(a));
    return lo + hi;
}

__device__ __forceinline__ unsigned long long pack2(float lo, float hi)
{
    unsigned long long u;
    asm("mov.b64 %0, {%1, %2};" : "=l"(u) : "f"(lo), "f"(hi));
    return u;
}

// ---------------------------------------------------------------------------
// 1) Node projections with f32x2-packed FMAs, paired over k.
//    sW[m][kp][d] = {W[2kp][d], W[2kp+1][d]}  (48 KB shared, pre-swizzled).
//    x row reinterpreted as 32 packed ulls {x[2k],x[2k+1]} — free pairing.
//    acc2[d] accumulates {sum over even k, sum over odd k}; final lo+hi.
// ---------------------------------------------------------------------------
__global__ __launch_bounds__(128) void proj_kernel(
    const float* __restrict__ X,
    const float* __restrict__ Wq,
    const float* __restrict__ Wk,
    const float* __restrict__ Wv)
{
    __shared__ unsigned long long sW[3][DD / 2][DD];   // 3*32*64*8 = 48 KB

    // Stage + k-pair-swizzle the weights (coalesced in d).
    for (int i = threadIdx.x; i < 3 * (DD / 2) * DD; i += 128) {
        int m  = i / ((DD / 2) * DD);
        int r  = i % ((DD / 2) * DD);
        int kp = r / DD;
        int d  = r % DD;
        const float* W = (m == 0) ? Wq : (m == 1) ? Wk : Wv;
        sW[m][kp][d] = pack2(W[(2 * kp) * DD + d], W[(2 * kp + 1) * DD + d]);
    }
    __syncthreads();

    int node = blockIdx.x * 128 + threadIdx.x;
    if (node >= NN) return;

    // Load x row as 16x 16B -> 32 packed ulls {x[2k], x[2k+1]}
    unsigned long long xp[DD / 2];
    const ulonglong2* xr = (const ulonglong2*)(X + (size_t)node * DD);
#pragma unroll
    for (int i = 0; i < DD / 8 * 2; i++) {
        ulonglong2 t = xr[i];
        xp[2 * i]     = t.x;
        xp[2 * i + 1] = t.y;
    }

    float* outs[3] = { g_Q + (size_t)node * DD,
                       g_K + (size_t)node * DD,
                       g_V + (size_t)node * DD };

#pragma unroll 1
    for (int m = 0; m < 3; m++) {
        float* out = outs[m];
#pragma unroll 1
        for (int dc = 0; dc < DD; dc += 8) {
            unsigned long long a0 = 0, a1 = 0, a2 = 0, a3 = 0,
                               a4 = 0, a5 = 0, a6 = 0, a7 = 0;
#pragma unroll
            for (int kp = 0; kp < DD / 2; kp++) {
                const unsigned long long* w = &sW[m][kp][dc];
                unsigned long long x2 = xp[kp];
                a0 = ffma2(x2, w[0], a0);
                a1 = ffma2(x2, w[1], a1);
                a2 = ffma2(x2, w[2], a2);
                a3 = ffma2(x2, w[3], a3);
                a4 = ffma2(x2, w[4], a4);
                a5 = ffma2(x2, w[5], a5);
                a6 = ffma2(x2, w[6], a6);
                a7 = ffma2(x2, w[7], a7);
            }
            float4 o0 = make_float4(unpack_sum(a0), unpack_sum(a1),
                                    unpack_sum(a2), unpack_sum(a3));
            float4 o1 = make_float4(unpack_sum(a4), unpack_sum(a5),
                                    unpack_sum(a6), unpack_sum(a7));
            *(float4*)(out + dc)     = o0;
            *(float4*)(out + dc + 4) = o1;
        }
    }
}

// ---------------------------------------------------------------------------
// 2) CSR build: zero counts -> histogram -> warp-shuffle scan -> scan sums ->
//    add offsets (+cursor init) -> scatter cols sorted by destination row.
// ---------------------------------------------------------------------------
__global__ void zero_cnt_kernel()
{
    int i = blockIdx.x * blockDim.x + threadIdx.x;
    if (i < NN) g_cnt[i] = 0;
}

__global__ void hist_kernel(const int* __restrict__ rows)
{
    int e = blockIdx.x * blockDim.x + threadIdx.x;
    if (e < EE) atomicAdd(&g_cnt[rows[e]], 1);
}

__global__ __launch_bounds__(1024) void scan_block_kernel()
{
    __shared__ int wsum[32];
    int i    = blockIdx.x * 1024 + threadIdx.x;
    int lane = threadIdx.x & 31;
    int w    = threadIdx.x >> 5;
    int v    = (i < NN) ? g_cnt[i] : 0;

    // warp inclusive scan
    int s = v;
#pragma unroll
    for (int o = 1; o < 32; o <<= 1) {
        int t = __shfl_up_sync(0xffffffffu, s, o);
        if (lane >= o) s += t;
    }
    if (lane == 31) wsum[w] = s;
    __syncthreads();

    if (w == 0) {
        int ws = wsum[lane];
        int t  = ws;
#pragma unroll
        for (int o = 1; o < 32; o <<= 1) {
            int u = __shfl_up_sync(0xffffffffu, t, o);
            if (lane >= o) t += u;
        }
        wsum[lane] = t - ws;   // exclusive warp prefix
    }
    __syncthreads();

    int incl = s + wsum[w];
    if (i < NN) g_off[i] = incl - v;                       // exclusive
    if (threadIdx.x == 1023) g_bsum[blockIdx.x] = incl;    // block total
}

__global__ void scan_sums_kernel(int nb)
{
    if (threadIdx.x == 0 && blockIdx.x == 0) {
        int acc = 0;
        for (int b = 0; b < nb; b++) { int t = g_bsum[b]; g_bsum[b] = acc; acc += t; }
    }
}

__global__ void add_off_kernel()
{
    int i = blockIdx.x * blockDim.x + threadIdx.x;
    if (i < NN) {
        int o = g_off[i] + g_bsum[i >> 10];
        g_off[i] = o;
        g_cur[i] = o;
    }
    if (i == 0) g_off[NN] = EE;
}

__global__ void scatter_kernel(const int* __restrict__ rows,
                               const int* __restrict__ cols)
{
    int e = blockIdx.x * blockDim.x + threadIdx.x;
    if (e < EE) {
        int p = atomicAdd(&g_cur[rows[e]], 1);
        g_scol[p] = cols[e];
    }
}

// ---------------------------------------------------------------------------
// 3) Fused attention aggregate: one warp per destination node, unrolled x4
//    with batched independent gathers (MLP=8) and interleaved shuffle trees.
// ---------------------------------------------------------------------------
__global__ __launch_bounds__(256) void aggregate_kernel(float* __restrict__ out)
{
    int warp = (blockIdx.x * blockDim.x + threadIdx.x) >> 5;
    int lane = threadIdx.x & 31;
    if (warp >= NN) return;

    int start = g_off[warp];
    int end   = g_off[warp + 1];

    float2 q   = *(const float2*)(g_Q + (size_t)warp * DD + lane * 2);
    float2 acc = make_float2(0.f, 0.f);
    float  na  = 0.f;

    int j = start;
    for (; j + 4 <= end; j += 4) {
        int c0 = __ldg(&g_scol[j + 0]);
        int c1 = __ldg(&g_scol[j + 1]);
        int c2 = __ldg(&g_scol[j + 2]);
        int c3 = __ldg(&g_scol[j + 3]);

        float2 k0 = *(const float2*)(g_K + (size_t)c0 * DD + lane * 2);
        float2 k1 = *(const float2*)(g_K + (size_t)c1 * DD + lane * 2);
        float2 k2 = *(const float2*)(g_K + (size_t)c2 * DD + lane * 2);
        float2 k3 = *(const float2*)(g_K + (size_t)c3 * DD + lane * 2);
        float2 v0 = *(const float2*)(g_V + (size_t)c0 * DD + lane * 2);
        float2 v1 = *(const float2*)(g_V + (size_t)c1 * DD + lane * 2);
        float2 v2 = *(const float2*)(g_V + (size_t)c2 * DD + lane * 2);
        float2 v3 = *(const float2*)(g_V + (size_t)c3 * DD + lane * 2);

        float p0 = q.x * k0.x + q.y * k0.y;
        float p1 = q.x * k1.x + q.y * k1.y;
        float p2 = q.x * k2.x + q.y * k2.y;
        float p3 = q.x * k3.x + q.y * k3.y;

        p0 += __shfl_xor_sync(0xffffffffu, p0, 1);
        p1 += __shfl_xor_sync(0xffffffffu, p1, 1);
        p2 += __shfl_xor_sync(0xffffffffu, p2, 1);
        p3 += __shfl_xor_sync(0xffffffffu, p3, 1);
        p0 += __shfl_xor_sync(0xffffffffu, p0, 2);
        p1 += __shfl_xor_sync(0xffffffffu, p1, 2);
        p2 += __shfl_xor_sync(0xffffffffu, p2, 2);
        p3 += __shfl_xor_sync(0xffffffffu, p3, 2);
        p0 += __shfl_xor_sync(0xffffffffu, p0, 4);
        p1 += __shfl_xor_sync(0xffffffffu, p1, 4);
        p2 += __shfl_xor_sync(0xffffffffu, p2, 4);
        p3 += __shfl_xor_sync(0xffffffffu, p3, 4);

        float e0 = __expf(fminf(10.f, fmaxf(-10.f, p0)));
        float e1 = __expf(fminf(10.f, fmaxf(-10.f, p1)));
        float e2 = __expf(fminf(10.f, fmaxf(-10.f, p2)));
        float e3 = __expf(fminf(10.f, fmaxf(-10.f, p3)));

        na += (e0 + e1) + (e2 + e3);
        acc.x += e0 * v0.x + e1 * v1.x + e2 * v2.x + e3 * v3.x;
        acc.y += e0 * v0.y + e1 * v1.y + e2 * v2.y + e3 * v3.y;
    }

    for (; j < end; j++) {
        int c = __ldg(&g_scol[j]);
        float2 k2v = *(const float2*)(g_K + (size_t)c * DD + lane * 2);
        float2 v2v = *(const float2*)(g_V + (size_t)c * DD + lane * 2);
        float p = q.x * k2v.x + q.y * k2v.y;
        p += __shfl_xor_sync(0xffffffffu, p, 1);
        p += __shfl_xor_sync(0xffffffffu, p, 2);
        p += __shfl_xor_sync(0xffffffffu, p, 4);
        float ea = __expf(fminf(10.f, fmaxf(-10.f, p)));
        na += ea;
        acc.x += ea * v2v.x;
        acc.y += ea * v2v.y;
    }

    float inv = 1.f / (na + 1e-8f);
    *(float2*)(out + (size_t)warp * DD + lane * 2) =
        make_float2(acc.x * inv, acc.y * inv);
}

// ---------------------------------------------------------------------------
extern "C" void kernel_launch(void* const* d_in, const int* in_sizes, int n_in,
                              void* d_out, int out_size)
{
    const float* X  = (const float*)d_in[0];
    const float* Wq = (const float*)d_in[1];
    const float* Wk = (const float*)d_in[2];
    const float* Wv = (const float*)d_in[3];
    const int*   ei = (const int*)d_in[4];
    const int* rows = ei;
    const int* cols = ei + EE;
    float* out = (float*)d_out;

    (void)in_sizes; (void)n_in; (void)out_size;

    // 1) node projections
    proj_kernel<<<(NN + 127) / 128, 128>>>(X, Wq, Wk, Wv);

    // 2) CSR build by destination row
    zero_cnt_kernel<<<(NN + 255) / 256, 256>>>();
    hist_kernel<<<(EE + 255) / 256, 256>>>(rows);
    int nb = (NN + 1023) / 1024;
    scan_block_kernel<<<nb, 1024>>>();
    scan_sums_kernel<<<1, 32>>>(nb);
    add_off_kernel<<<(NN + 255) / 256, 256>>>();
    scatter_kernel<<<(EE + 255) / 256, 256>>>(rows, cols);

    // 3) fused gather + softmax + aggregate (one warp per node)
    aggregate_kernel<<<(NN * 32 + 255) / 256, 256>>>(out);
}